// round 17
// baseline (speedup 1.0000x reference)
#include <cuda_runtime.h>
#include <cuda_fp16.h>
#include <cstdint>
#include <cfloat>
#include <math.h>

typedef unsigned long long u64;
typedef unsigned int u32;

#define DHALF 64
#define DFULL 128
#define KCODES 512
#define MTILE 64
#define NTHREADS 256

// Device-global scratch (allocation-free per harness rules)
__device__ float g_nt[KCODES];
__device__ float g_dw[KCODES * DFULL];
__device__ float g_ysq[KCODES];
__device__ __half g_hw[KCODES * DFULL];   // fp16 codebook, pre-scaled by 512

// ---------------------------------------------------------------------------
// Warp-level primitives (plain sm_80+ PTX; compute_103-safe)
// ---------------------------------------------------------------------------
__device__ __forceinline__ u32 smem_u32(const void* p) {
    u32 a;
    asm("{ .reg .u64 t; cvta.to.shared.u64 t, %1; cvt.u32.u64 %0, t; }"
        : "=r"(a) : "l"(p));
    return a;
}

#define LDSM_X4(r, addr) \
    asm volatile("ldmatrix.sync.aligned.m8n8.x4.shared.b16 {%0,%1,%2,%3}, [%4];" \
                 : "=r"((r)[0]), "=r"((r)[1]), "=r"((r)[2]), "=r"((r)[3]) \
                 : "r"(addr))

#define MMA16816F16(d, a, b0, b1) \
    asm volatile("mma.sync.aligned.m16n8k16.row.col.f32.f16.f16.f32 " \
                 "{%0,%1,%2,%3},{%4,%5,%6,%7},{%8,%9},{%0,%1,%2,%3};" \
                 : "+f"((d)[0]), "+f"((d)[1]), "+f"((d)[2]), "+f"((d)[3]) \
                 : "r"((a)[0]), "r"((a)[1]), "r"((a)[2]), "r"((a)[3]), \
                   "r"(b0), "r"(b1))

#define REDG_V4(ptr, v) \
    asm volatile("red.global.add.v4.f32 [%0], {%1,%2,%3,%4};" \
                 :: "l"(ptr), "f"((v).x), "f"((v).y), "f"((v).z), "f"((v).w) \
                 : "memory")

// Sortable-float transform (ascending u32 order == ascending float order)
__device__ __forceinline__ u32 fsort(float f) {
    u32 fb = __float_as_uint(f);
    return fb ^ ((u32)((int)fb >> 31) | 0x80000000u);
}
__device__ __forceinline__ float funsort(u32 k) {
    u32 fb = (k & 0x80000000u) ? (k ^ 0x80000000u) : ~k;
    return __uint_as_float(fb);
}
// Branchless insert into ascending-sorted u32 triple (IMNMX only, no branches)
__device__ __forceinline__ void ins3u(u32* t, u32 x) {
    u32 a = min(t[0], x), b = max(t[0], x); t[0] = a;
    u32 c = min(t[1], b), e = max(t[1], b); t[1] = c;
    t[2] = min(t[2], e);
}

// ---------------------------------------------------------------------------
// Stage 0: y_sq (reference fp32 order), zero accumulators, fp16 codebook
// pre-scaled by 512 (exact pow2; 512*w in (-1,1) -> fp16 rel err 2^-11).
// ---------------------------------------------------------------------------
__global__ void vq_prep(const float* __restrict__ emb) {
    int b = blockIdx.x, t = threadIdx.x;
    size_t e = (size_t)b * DFULL + t;
    float f = emb[e];
    g_hw[e] = __float2half_rn(__fmul_rn(f, 512.0f));
    g_dw[e] = 0.f;
    if (t == 0) {
        g_nt[b] = 0.f;
        const float* w = emb + (size_t)b * DFULL;
        float s = 0.f;
        #pragma unroll 8
        for (int d = 0; d < DFULL; d++) s = __fadd_rn(s, __fmul_rn(w[d], w[d]));
        g_ysq[b] = s;
    }
}

// ---------------------------------------------------------------------------
// Smem layout. A tile only: XOR-swizzled 8x8-atom layout. Atom (r8, katom) at
// ((r8*16 + katom)*128) bytes; row r within the atom at 16B slot
// ((r&7) ^ (katom&7)) -> conflict-free ldmatrix AND conflict-free stores.
// B never touches smem: fragments are LDG'd straight from the L1-resident
// fp16 codebook (128 KB read-only) -> zero barriers in the main loop.
// ---------------------------------------------------------------------------
static constexpr int SM_TOP3 = 0;        // 64 rows x 4 quads x 3 u32 = 3072
static constexpr int SM_XSQ  = 3072;     // 64 f32
static constexpr int SM_YSQ  = 3328;     // 512 f32
static constexpr int SM_RESK = 5376;     // 64 int
static constexpr int SM_A    = 8192;     // 16384 (64x128 fp16)
static constexpr int SM_TOTAL = 24576;

// ---------------------------------------------------------------------------
// Stage 1: single-term fp16 HMMA filter (B fragments from global/L1) ->
// register-persistent top-3 per (row, quadrant) -> exact fp32 rescore
// (near-tie rows only) -> outputs + segment sums.
// One CTA per 64-row tile; 256 threads = 8 warps (2m x 4n), 32x32 tiles.
// ---------------------------------------------------------------------------
__global__ void __launch_bounds__(NTHREADS, 3)
vq_main(const float* __restrict__ zr, const float* __restrict__ zi,
        const float* __restrict__ emb,
        float* __restrict__ o_zqr, float* __restrict__ o_zqi,
        float* __restrict__ o_loss, float* __restrict__ o_idx)
{
    extern __shared__ char sm[];
    const u32 smb = smem_u32(sm);
    const int tid  = threadIdx.x;
    const int wid  = tid >> 5, lane = tid & 31;
    const int wm   = wid & 1,  wn   = wid >> 1;
    const int row0 = blockIdx.x * MTILE;

    u32*   top3  = (u32*)(sm + SM_TOP3);
    float* xsq_s = (float*)(sm + SM_XSQ);
    float* ysq_s = (float*)(sm + SM_YSQ);
    int*   resk  = (int*)(sm + SM_RESK);

    #pragma unroll
    for (int i = tid; i < KCODES; i += NTHREADS) ysq_s[i] = g_ysq[i];

    // A tile: z rows (real -> k 0-63, imag -> k 64-127) as fp16, swizzled
    // atom layout. katom = q>>1; slot xor key = katom&7.
    for (int i = tid; i < MTILE * 32; i += NTHREADS) {
        int row = i >> 5, q = i & 31;
        const float* src = (q < 16) ? (zr + (size_t)(row0 + row) * DHALF + q * 4)
                                    : (zi + (size_t)(row0 + row) * DHALF + (q - 16) * 4);
        float4 v = *(const float4*)src;
        int katom = q >> 1;
        u32 off = (u32)(((row >> 3) * 16 + katom) * 128
                        + (((row & 7) ^ (katom & 7)) * 16) + (q & 1) * 8);
        unsigned short h[4];
        #pragma unroll
        for (int e2 = 0; e2 < 4; e2++)
            h[e2] = __half_as_ushort(__float2half_rn((&v.x)[e2]));
        *(u64*)(sm + SM_A + off) = (u64)h[0] | ((u64)h[1] << 16)
                                 | ((u64)h[2] << 32) | ((u64)h[3] << 48);
    }

    // x_sq per row: sequential fp32 in reference order (real then imag)
    if (tid < MTILE) {
        const float* a = zr + (size_t)(row0 + tid) * DHALF;
        const float* b = zi + (size_t)(row0 + tid) * DHALF;
        float s = 0.f;
        #pragma unroll 8
        for (int d = 0; d < DHALF; d++) s = __fadd_rn(s, __fmul_rn(a[d], a[d]));
        #pragma unroll 8
        for (int d = 0; d < DHALF; d++) s = __fadd_rn(s, __fmul_rn(b[d], b[d]));
        xsq_s[tid] = s;
    }

    // Per-lane A ldmatrix address pieces (xor-swizzle aware).
    const int l7 = lane & 7;
    const int a_mb = (lane >> 3) & 1;        // A: m+8 selector
    const int a_kb = (lane >> 4) & 1;        // A: k-atom parity
    const u32 ra16 = (u32)((l7 ^ a_kb) * 16);
    const u32 Apre = smb + SM_A + wm * 8192 + a_mb * 2048 + a_kb * 128;
    const int l4 = lane >> 2, lc = (lane & 3) * 2;

    // Per-lane B fragment source: PTX m16n8k16 B layout (row.col):
    //   b0 holds B[2*(lane%4)+{0,1}][lane/4], b1 same at k+8.
    // g_hw is [code][k] with k contiguous -> per fragment two LDG.32.
    const __half* Bbase = g_hw + (size_t)(wn * 32 + l4) * DFULL + lc;

    // Register-persistent top-3 triples, one per (mt, rh) row-group.
    u32 trip[4][3];
    #pragma unroll
    for (int gi = 0; gi < 4; gi++)
        trip[gi][0] = trip[gi][1] = trip[gi][2] = 0xFFFFFFFFu;

    __syncthreads();   // A tile + xsq + ysq visible; no barriers after this
                       // until the candidate merge.

    for (int c = 0; c < 4; c++) {
        const __half* Bg = Bbase + (size_t)c * 128 * DFULL;

        float d[2][4][4];
        #pragma unroll
        for (int mt = 0; mt < 2; mt++)
            #pragma unroll
            for (int nt = 0; nt < 4; nt++)
                #pragma unroll
                for (int e2 = 0; e2 < 4; e2++) d[mt][nt][e2] = 0.f;

        #pragma unroll
        for (int ks = 0; ks < 8; ks++) {
            const u32 c16 = (u32)((ks & 3) * 32);   // ((2ks)&7)*16
            u32 Aad = Apre + ks * 256 + (ra16 ^ c16);
            u32 a0[4], a1[4], b0[4], b1[4];
            LDSM_X4(a0, Aad);
            LDSM_X4(a1, Aad + 4096);
            #pragma unroll
            for (int nt = 0; nt < 4; nt++) {
                const __half* p = Bg + nt * 8 * DFULL + ks * 16;
                b0[nt] = __ldg((const u32*)p);
                b1[nt] = __ldg((const u32*)(p + 8));
            }
            #pragma unroll
            for (int nt = 0; nt < 4; nt++) {
                MMA16816F16(d[0][nt], a0, b0[nt], b1[nt]);
                MMA16816F16(d[1][nt], a1, b0[nt], b1[nt]);
            }
        }

        // Chunk epilogue: dist' = 256*y_sq - d  (= 256*(dist - x_sq), x_sq
        // constant per row -> order-preserving). Quantized sortable key with
        // the 9-bit code in the low bits; branchless triple insert.
        #pragma unroll
        for (int mt = 0; mt < 2; mt++) {
            #pragma unroll
            for (int rh = 0; rh < 2; rh++) {
                u32* t = trip[mt * 2 + rh];
                #pragma unroll
                for (int nt = 0; nt < 4; nt++) {
                    #pragma unroll
                    for (int cl = 0; cl < 2; cl++) {
                        int code = c * 128 + wn * 32 + nt * 8 + lc + cl;
                        float dp = __fmaf_rn(256.0f, ysq_s[code],
                                             -d[mt][nt][rh * 2 + cl]);
                        ins3u(t, (fsort(dp) & 0xFFFFFE00u) | (u32)code);
                    }
                }
            }
        }
    }

    // Final merge: shfl across the 4 lanes sharing a row, owner writes smem.
    #pragma unroll
    for (int gi = 0; gi < 4; gi++) {
        u32 t[3] = {trip[gi][0], trip[gi][1], trip[gi][2]};
        #pragma unroll
        for (int off = 1; off <= 2; off <<= 1) {
            u32 o0 = __shfl_xor_sync(0xffffffffu, t[0], off);
            u32 o1 = __shfl_xor_sync(0xffffffffu, t[1], off);
            u32 o2 = __shfl_xor_sync(0xffffffffu, t[2], off);
            ins3u(t, o0); ins3u(t, o1); ins3u(t, o2);
        }
        if ((lane & 3) == 0) {
            int row = wm * 32 + (gi >> 1) * 16 + (gi & 1) * 8 + l4;
            u32* s = &top3[(row * 4 + wn) * 3];
            s[0] = t[0]; s[1] = t[1]; s[2] = t[2];
        }
    }
    __syncthreads();

    // Decision phase: 4 threads per row. Accept the approx winner only when
    // the approx top-2 dist'-gap exceeds 0.256 (= 1e-3 in dist units, ~40x
    // the filter error: fp16 inputs ~2.4e-5 rms + 4e-6 key quantization).
    // Otherwise rescore all 12 candidates in exact fp32 (float4-vectorized,
    // same k-order) and take the lexicographic (dist, idx) min ==
    // jnp.argmin first-min semantics.
    {
        int row = tid >> 2, part = tid & 3;
        size_t n = (size_t)row0 + row;
        u32* slot = top3 + row * 12;
        u32 c0 = 0xFFFFFFFFu, c1 = 0xFFFFFFFFu;
        int cidx[12];
        #pragma unroll
        for (int i = 0; i < 12; i++) {
            u32 x = slot[i];
            cidx[i] = (int)(x & 511u);
            u32 a = min(c0, x), b = max(c0, x);
            c0 = a; c1 = min(c1, b);
        }
        int widx;
        float f0 = funsort(c0 & 0xFFFFFE00u);
        float f1 = funsort(c1 & 0xFFFFFE00u);
        if (__fsub_rn(f1, f0) > 0.256f) {
            widx = (int)(c0 & 511u);
        } else {
            const u32 gmask = 0xFu << (lane & 28);
            const float* zp = (part < 2) ? (zr + n * DHALF + part * 32)
                                         : (zi + n * DHALF + (part - 2) * 32);
            float acc[12];
            #pragma unroll
            for (int i = 0; i < 12; i++) acc[i] = 0.f;
            for (int dd = 0; dd < 32; dd += 4) {
                float4 zv = *(const float4*)(zp + dd);
                #pragma unroll
                for (int i = 0; i < 12; i++) {
                    float4 wv = *(const float4*)(emb
                        + (size_t)cidx[i] * DFULL + part * 32 + dd);
                    float a2 = acc[i];
                    a2 = __fmaf_rn(zv.x, wv.x, a2);
                    a2 = __fmaf_rn(zv.y, wv.y, a2);
                    a2 = __fmaf_rn(zv.z, wv.z, a2);
                    a2 = __fmaf_rn(zv.w, wv.w, a2);
                    acc[i] = a2;
                }
            }
            #pragma unroll
            for (int off = 1; off <= 2; off <<= 1)
                #pragma unroll
                for (int i = 0; i < 12; i++)
                    acc[i] = __fadd_rn(acc[i],
                                       __shfl_xor_sync(gmask, acc[i], off));
            float xs = xsq_s[row];
            u64 bp = ~0ull;
            #pragma unroll
            for (int i = 0; i < 12; i++) {
                float dist = __fmaf_rn(-2.0f, acc[i],
                                       __fadd_rn(xs, ysq_s[cidx[i]]));
                u64 p = ((u64)fsort(dist) << 32) | (u32)cidx[i];
                bp = min(bp, p);
            }
            widx = (int)(u32)(bp & 511u);
        }
        if (part == 0) resk[row] = widx;
    }
    __syncthreads();

    // Phase 2: per-row outputs + segment accumulation. 4 threads per row.
    {
        int row = tid >> 2, part = tid & 3;
        size_t n = (size_t)row0 + row;
        int idx = resk[row];
        const float* wp  = emb + (size_t)idx * DFULL + part * 32;
        const float* zp  = (part < 2) ? (zr + n * DHALF + part * 32)
                                      : (zi + n * DHALF + (part - 2) * 32);
        float* dwp = g_dw + (size_t)idx * DFULL + part * 32;
        float* oz  = (part < 2) ? (o_zqr + n * DHALF + part * 32)
                                : (o_zqi + n * DHALF + (part - 2) * 32);
        float ls = 0.f;
        #pragma unroll
        for (int q = 0; q < 8; q++) {
            float4 zv4 = *(const float4*)(zp + q * 4);
            float4 o;
            #pragma unroll
            for (int e2 = 0; e2 < 4; e2++) {
                float zv = (&zv4.x)[e2];
                float wv = __ldg(wp + q * 4 + e2);
                float dv = __fsub_rn(wv, zv);
                ls = __fadd_rn(ls, __fmul_rn(dv, dv));
                (&o.x)[e2] = __fadd_rn(zv, dv);   // z + (z_q - z): straight-through
            }
            REDG_V4(dwp + q * 4, zv4);
            *(float4*)(oz + q * 4) = o;
        }
        ls = __fadd_rn(ls, __shfl_xor_sync(0xffffffffu, ls, 1));
        ls = __fadd_rn(ls, __shfl_xor_sync(0xffffffffu, ls, 2));
        if (part == 0) {
            o_loss[n] = __fmul_rn(0.25f, __fmul_rn(ls, (1.0f / 128.0f)));
            o_idx[n]  = (float)idx;
            atomicAdd(&g_nt[idx], 1.0f);
        }
    }
}

// ---------------------------------------------------------------------------
// Stage 2: EMA update, cluster-size normalization, entropy. 1 block x 512.
// ---------------------------------------------------------------------------
__global__ void vq_final(const float* __restrict__ ecs, const float* __restrict__ emaw,
                         float* __restrict__ o_ent, float* __restrict__ o_emb,
                         float* __restrict__ o_nc,  float* __restrict__ o_ema)
{
    __shared__ float red[512];
    int k = threadIdx.x;
    const float DEC = 0.99f;
    const float OM  = (float)(1.0 - 0.99);

    float ntv = g_nt[k];
    float nc  = __fadd_rn(__fmul_rn(ecs[k], DEC), __fmul_rn(OM, ntv));
    o_nc[k] = nc;

    red[k] = nc;
    __syncthreads();
    for (int s = 256; s > 0; s >>= 1) {
        if (k < s) red[k] = __fadd_rn(red[k], red[k + s]);
        __syncthreads();
    }
    float tot = red[0];
    __syncthreads();

    float csz = __fmul_rn(__fdiv_rn(__fadd_rn(nc, 1e-5f),
                                    __fadd_rn(tot, (float)(512 * 1e-5))), tot);

    for (int d = 0; d < DFULL; d++) {
        float ne = __fadd_rn(__fmul_rn(emaw[(size_t)k * DFULL + d], DEC),
                             __fmul_rn(OM, g_dw[(size_t)k * DFULL + d]));
        o_ema[(size_t)k * DFULL + d] = ne;
        o_emb[(size_t)k * DFULL + d] = __fdiv_rn(ne, csz);
    }

    float p = __fdiv_rn(ntv, 262144.0f);
    float t = __fmul_rn(p, logf(__fadd_rn(p, 1e-10f)));
    red[k] = t;
    __syncthreads();
    for (int s = 256; s > 0; s >>= 1) {
        if (k < s) red[k] = __fadd_rn(red[k], red[k + s]);
        __syncthreads();
    }
    if (k == 0) o_ent[0] = __fdiv_rn(-red[0], 6.2383246250395075f);  // / log(512)
}

// ---------------------------------------------------------------------------
extern "C" void kernel_launch(void* const* d_in, const int* in_sizes, int n_in,
                              void* d_out, int out_size)
{
    const float* zr   = (const float*)d_in[0];
    const float* zi   = (const float*)d_in[1];
    const float* emb  = (const float*)d_in[2];
    const float* ecs  = (const float*)d_in[3];
    const float* emaw = (const float*)d_in[4];
    float* out = (float*)d_out;

    size_t nrows = (size_t)in_sizes[0] / DHALF;   // 262144

    // Output layout = reference return tuple, flattened + concatenated
    float* o_zqr  = out;
    float* o_zqi  = o_zqr + nrows * DHALF;
    float* o_loss = o_zqi + nrows * DHALF;
    float* o_idx  = o_loss + nrows;
    float* o_ent  = o_idx + nrows;
    float* o_emb  = o_ent + 1;
    float* o_nc   = o_emb + (size_t)KCODES * DFULL;
    float* o_ema  = o_nc + KCODES;

    vq_prep<<<KCODES, DFULL>>>(emb);

    cudaFuncSetAttribute(vq_main, cudaFuncAttributeMaxDynamicSharedMemorySize,
                         SM_TOTAL);
    vq_main<<<(unsigned)(nrows / MTILE), NTHREADS, SM_TOTAL>>>(
        zr, zi, emb, o_zqr, o_zqi, o_loss, o_idx);

    vq_final<<<1, 512>>>(ecs, emaw, o_ent, o_emb, o_nc, o_ema);
}